// round 10
// baseline (speedup 1.0000x reference)
#include <cuda_runtime.h>
#include <cfloat>

// Problem constants (from reference)
#define PB 7      // pooled bins per dim
#define HH 50
#define WW 50
#define CC 512
#define BB 2
#define RR 64
#define C4 (CC / 4)   // 128 float4 per pixel

// One CTA per (b, r, py, px) output bin; 128 threads, one float4 channel
// slice each. MECHANISM CHANGE vs all prior rounds: the sy*sx (<=16) pixel
// gather is done with cp.async (LDGSTS) into shared memory — fire-and-forget
// 16B copies with no destination register, so ALL pixels are in flight at
// once irrespective of the register budget (which ptxas used to serialize
// the LDG version down to ~4 in flight). Each thread copies and then reads
// back only its own 16B slots, so no __syncthreads is needed — only
// cp.async.wait_group 0.
//
// Bin bounds use integer arithmetic ys = py*h/7 etc. For h in [7,25] and
// py in [0,6] this is exactly equal to the reference's fp32
// trunc(py * (h/7.0f)): when 7|h the fp32 path is exact; when 7 does not
// divide h, py*h/7 is at distance >= 1/7 from any nonzero integer, vastly
// larger than the fp32 rounding error (~3e-6), so the floor matches.
//
// Facts proved from input ranges: extent in [7,26) => sy,sx in [1,4];
// window always fully in-bounds (max index y0+h-1 <= 48 < 50).

__device__ __forceinline__ void vmax(float4& m, float4 v) {
    m.x = fmaxf(m.x, v.x);
    m.y = fmaxf(m.y, v.y);
    m.z = fmaxf(m.z, v.z);
    m.w = fmaxf(m.w, v.w);
}

__device__ __forceinline__ void cp_async16(unsigned smem_addr, const void* gptr) {
    asm volatile("cp.async.cg.shared.global [%0], [%1], 16;"
                 :: "r"(smem_addr), "l"(gptr) : "memory");
}

__global__ __launch_bounds__(C4) void roipool_kernel(
    const float4* __restrict__ fm,    // (B,H,W,C) as float4
    const int*    __restrict__ rois,  // (B,R,4) int32: y0,x0,h,w
    float4*       __restrict__ out)   // (B,R,P,P,C) as float4
{
    __shared__ alignas(16) float4 buf[16 * C4];   // 32 KB: 16 pixels x 128 slices

    int idx = blockIdx.x;                 // b*R*P*P + r*P*P + py*P + px
    int px = idx % PB;
    int t  = idx / PB;
    int py = t % PB;
    t /= PB;
    int r = t % RR;
    int b = t / RR;

    const int4 roi = __ldg((const int4*)(rois + (b * RR + r) * 4));
    int y0 = roi.x, x0 = roi.y, h = roi.z, w = roi.w;

    // Integer bin bounds (== reference fp32 result, see header comment).
    int ys = (py * h) / PB;
    int ye = (py == PB - 1) ? h : ((py + 1) * h) / PB;
    int sy = max(ye - ys, 1);
    int xs = (px * w) / PB;
    int xe = (px == PB - 1) ? w : ((px + 1) * w) / PB;
    int sx = max(xe - xs, 1);

    int c4 = threadIdx.x;  // 0..127

    const float4* p = fm
        + ((size_t)((b * HH + (y0 + ys)) * WW + (x0 + xs))) * C4
        + c4;

    // Fire all sy*sx pixel copies (each 16B for this thread), no registers held.
    unsigned sbase = (unsigned)__cvta_generic_to_shared(&buf[c4]);
    int k = 0;
    for (int dy = 0; dy < sy; ++dy) {
        const float4* rowp = p + dy * (WW * C4);
        for (int dx = 0; dx < sx; ++dx) {
            cp_async16(sbase + (unsigned)k * (C4 * 16), rowp + dx * C4);
            ++k;
        }
    }
    asm volatile("cp.async.commit_group;" ::: "memory");
    asm volatile("cp.async.wait_group 0;" ::: "memory");

    // Reduce this thread's slots from smem (conflict-free: warp reads 512B rows).
    int n = sy * sx;
    float4 m = buf[c4];
    for (int j = 1; j < n; ++j)
        vmax(m, buf[j * C4 + c4]);

    out[(size_t)idx * C4 + c4] = m;
}

extern "C" void kernel_launch(void* const* d_in, const int* in_sizes, int n_in,
                              void* d_out, int out_size) {
    const float4* fm   = (const float4*)d_in[0];  // x_maps float32 (2,50,50,512)
    const int*    rois = (const int*)d_in[1];     // x_rois int32 (2,64,4)
    float4*       out  = (float4*)d_out;          // (2,64,7,7,512) float32

    int nblocks = BB * RR * PB * PB;  // 6272
    roipool_kernel<<<nblocks, C4>>>(fm, rois, out);
}

// round 11
// speedup vs baseline: 1.1237x; 1.1237x over previous
#include <cuda_runtime.h>
#include <cfloat>

// Problem constants (from reference)
#define PB 7      // pooled bins per dim
#define HH 50
#define WW 50
#define CC 512
#define BB 2
#define RR 64
#define C4 (CC / 4)   // 128 float4 per pixel

// One WARP per (b, r, py, px) output bin; 4 warps per 128-thread CTA.
// Each lane owns 4 float4 channel slices: c4 = lane + 32*i, i in 0..3.
// Per pixel the warp loads the full contiguous 2KB (identical coalescing and
// total traffic as before), but each thread now carries 4 INDEPENDENT
// accumulator chains -> every pixel issues 4 scoreboard-independent LDG.128,
// giving steady MLP >= 4 per thread at ~50 regs with no occupancy price
// (grid 1568 x 128 = 42 warps/SM: full single-wave residency).
//
// (sy,sx) is uniform per warp -> the 16-case exact-load switch is
// divergence-free.
//
// Facts proved from input ranges: extent in [7,26) => sy,sx in [1,4];
// window always fully in-bounds (max index y0+h-1 <= 48 < 50).
//
// Integer bin bounds ys = py*h/7 etc. equal the reference's fp32
// trunc(py * (h/7.0f)) for h in [7,25]: exact when 7|h; otherwise py*h/7 is
// >= 1/7 away from any integer, far beyond fp32 rounding error, so the
// truncation matches. (Validated rel_err = 0.0 in round 10.)

__device__ __forceinline__ void vmax(float4& m, float4 v) {
    m.x = fmaxf(m.x, v.x);
    m.y = fmaxf(m.y, v.y);
    m.z = fmaxf(m.z, v.z);
    m.w = fmaxf(m.w, v.w);
}

template<int SY, int SX>
__device__ __forceinline__ void binmax4(const float4* __restrict__ p, float4 m[4]) {
    // First pixel initializes the 4 chains.
    #pragma unroll
    for (int i = 0; i < 4; ++i)
        m[i] = __ldg(p + 32 * i);

    #pragma unroll
    for (int k = 1; k < SY * SX; ++k) {
        const int dy = k / SX, dx = k % SX;
        const float4* q = p + (dy * WW + dx) * C4;
        #pragma unroll
        for (int i = 0; i < 4; ++i)
            vmax(m[i], __ldg(q + 32 * i));
    }
}

__global__ __launch_bounds__(128) void roipool_kernel(
    const float4* __restrict__ fm,    // (B,H,W,C) as float4
    const int*    __restrict__ rois,  // (B,R,4) int32: y0,x0,h,w
    float4*       __restrict__ out)   // (B,R,P,P,C) as float4
{
    int lane = threadIdx.x & 31;
    int warp = threadIdx.x >> 5;

    int idx = blockIdx.x * 4 + warp;      // global bin id, 0..6271
    int px = idx % PB;
    int t  = idx / PB;
    int py = t % PB;
    t /= PB;
    int r = t % RR;
    int b = t / RR;

    const int4 roi = __ldg((const int4*)(rois + (b * RR + r) * 4));
    int y0 = roi.x, x0 = roi.y, h = roi.z, w = roi.w;

    // Integer bin bounds (== reference fp32 result, see header comment).
    int ys = (py * h) / PB;
    int ye = (py == PB - 1) ? h : ((py + 1) * h) / PB;
    int sy = max(ye - ys, 1);
    int xs = (px * w) / PB;
    int xe = (px == PB - 1) ? w : ((px + 1) * w) / PB;
    int sx = max(xe - xs, 1);

    const float4* p = fm
        + ((size_t)((b * HH + (y0 + ys)) * WW + (x0 + xs))) * C4
        + lane;

    float4 m[4];
    int code = (sy - 1) * 4 + (sx - 1);   // uniform per warp: no divergence
    switch (code) {
        case  0: binmax4<1,1>(p, m); break;
        case  1: binmax4<1,2>(p, m); break;
        case  2: binmax4<1,3>(p, m); break;
        case  3: binmax4<1,4>(p, m); break;
        case  4: binmax4<2,1>(p, m); break;
        case  5: binmax4<2,2>(p, m); break;
        case  6: binmax4<2,3>(p, m); break;
        case  7: binmax4<2,4>(p, m); break;
        case  8: binmax4<3,1>(p, m); break;
        case  9: binmax4<3,2>(p, m); break;
        case 10: binmax4<3,3>(p, m); break;
        case 11: binmax4<3,4>(p, m); break;
        case 12: binmax4<4,1>(p, m); break;
        case 13: binmax4<4,2>(p, m); break;
        case 14: binmax4<4,3>(p, m); break;
        default: binmax4<4,4>(p, m); break;
    }

    float4* o = out + (size_t)idx * C4 + lane;
    #pragma unroll
    for (int i = 0; i < 4; ++i)
        o[32 * i] = m[i];
}

extern "C" void kernel_launch(void* const* d_in, const int* in_sizes, int n_in,
                              void* d_out, int out_size) {
    const float4* fm   = (const float4*)d_in[0];  // x_maps float32 (2,50,50,512)
    const int*    rois = (const int*)d_in[1];     // x_rois int32 (2,64,4)
    float4*       out  = (float4*)d_out;          // (2,64,7,7,512) float32

    int nblocks = (BB * RR * PB * PB) / 4;  // 1568
    roipool_kernel<<<nblocks, 128>>>(fm, rois, out);
}

// round 12
// speedup vs baseline: 1.3103x; 1.1661x over previous
#include <cuda_runtime.h>
#include <cfloat>

// Problem constants (from reference)
#define PB 7      // pooled bins per dim
#define HH 50
#define WW 50
#define CC 512
#define BB 2
#define RR 64
#define C4 (CC / 4)     // 128 float4 per pixel
#define NBINS (BB * RR * PB * PB)   // 6272
#define NCTA  (NBINS / 4)           // 1568: 4 bins per CTA

// R5 structure (best: 10.27us) with two micro-fixes:
//  * integer bin bounds  ys = py*h/7 (== reference fp32 trunc(py*(h/7.0f))
//    for h in [7,25]: exact when 7|h, else py*h/7 is >=1/7 from any integer,
//    far beyond fp32 rounding error; validated rel_err=0.0 in R10/R11) —
//    removes the dependent I2F/FMUL/F2I chain gating the gather addresses.
//  * roi for iteration k+1 is loaded before iteration k's gather, so its L2
//    latency is covered by the gather instead of sitting on the chain.
//
// CTA i handles bins {i, i+1568, i+3136, i+4704}. 1568 = 32*49, so all 4
// bins share one (py,px) — decoded once — and rid advances by 32.
// Each thread owns one float4 channel slice; (sy,sx) is CTA-uniform so the
// 16-case exact-load dispatch has no divergence.
//
// Facts proved from input ranges: extent in [7,26) => sy,sx in [1,4];
// window always fully in-bounds (max index y0+h-1 <= 48 < 50).

__device__ __forceinline__ void vmax(float4& m, float4 v) {
    m.x = fmaxf(m.x, v.x);
    m.y = fmaxf(m.y, v.y);
    m.z = fmaxf(m.z, v.z);
    m.w = fmaxf(m.w, v.w);
}

template<int SY, int SX>
__device__ __forceinline__ float4 binmax(const float4* __restrict__ p) {
    float4 v[SY * SX];
    #pragma unroll
    for (int dy = 0; dy < SY; ++dy)
        #pragma unroll
        for (int dx = 0; dx < SX; ++dx)
            v[dy * SX + dx] = __ldg(p + (dy * WW + dx) * C4);

    float4 m = v[0];
    #pragma unroll
    for (int k = 1; k < SY * SX; ++k)
        vmax(m, v[k]);
    return m;
}

__global__ __launch_bounds__(C4) void roipool_kernel(
    const float4* __restrict__ fm,    // (B,H,W,C) as float4
    const int*    __restrict__ rois,  // (B,R,4) int32: y0,x0,h,w
    float4*       __restrict__ out)   // (B,R,P,P,C) as float4
{
    int binbase = blockIdx.x;         // 0..1567
    int px   = binbase % PB;
    int py   = (binbase / PB) % PB;
    int rid0 = binbase / (PB * PB);   // 0..31; iterations use rid0 + 32k

    int c4 = threadIdx.x;             // 0..127
    bool lasty = (py == PB - 1);
    bool lastx = (px == PB - 1);
    int obin = py * PB + px;

    // First roi load issues immediately.
    int4 roi = __ldg((const int4*)(rois + rid0 * 4));

    #pragma unroll
    for (int k = 0; k < 4; ++k) {
        int rid = rid0 + 32 * k;

        // Issue next roi load BEFORE this bin's gather so its latency is
        // covered by the gather's loads.
        int4 roi_n;
        if (k < 3)
            roi_n = __ldg((const int4*)(rois + (rid + 32) * 4));

        int y0 = roi.x, x0 = roi.y, h = roi.z, w = roi.w;

        // Integer bin bounds (== reference fp32 result, see header).
        int ys = (py * h) / PB;
        int ye = lasty ? h : ((py + 1) * h) / PB;
        int sy = max(ye - ys, 1);
        int xs = (px * w) / PB;
        int xe = lastx ? w : ((px + 1) * w) / PB;
        int sx = max(xe - xs, 1);

        // b = rid >> 6; fm image stride = HH*WW pixels.
        const float4* p = fm
            + ((size_t)(((rid >> 6) * HH + (y0 + ys)) * WW + (x0 + xs))) * C4
            + c4;

        float4 m;
        int code = (sy - 1) * 4 + (sx - 1);   // uniform across CTA
        switch (code) {
            case  0: m = binmax<1,1>(p); break;
            case  1: m = binmax<1,2>(p); break;
            case  2: m = binmax<1,3>(p); break;
            case  3: m = binmax<1,4>(p); break;
            case  4: m = binmax<2,1>(p); break;
            case  5: m = binmax<2,2>(p); break;
            case  6: m = binmax<2,3>(p); break;
            case  7: m = binmax<2,4>(p); break;
            case  8: m = binmax<3,1>(p); break;
            case  9: m = binmax<3,2>(p); break;
            case 10: m = binmax<3,3>(p); break;
            case 11: m = binmax<3,4>(p); break;
            case 12: m = binmax<4,1>(p); break;
            case 13: m = binmax<4,2>(p); break;
            case 14: m = binmax<4,3>(p); break;
            default: m = binmax<4,4>(p); break;
        }

        out[(size_t)(rid * (PB * PB) + obin) * C4 + c4] = m;

        roi = roi_n;
    }
}

extern "C" void kernel_launch(void* const* d_in, const int* in_sizes, int n_in,
                              void* d_out, int out_size) {
    const float4* fm   = (const float4*)d_in[0];  // x_maps float32 (2,50,50,512)
    const int*    rois = (const int*)d_in[1];     // x_rois int32 (2,64,4)
    float4*       out  = (float4*)d_out;          // (2,64,7,7,512) float32

    roipool_kernel<<<NCTA, C4>>>(fm, rois, out);
}